// round 7
// baseline (speedup 1.0000x reference)
#include <cuda_runtime.h>
#include <stdint.h>

#define CIN   320
#define COUT  320
#define KTAPS 9
#define NPIX  65536
#define HWSZ  4096

// scratch (__device__ globals: allocation-free rule)
__device__ __align__(128) int8_t g_xq[(size_t)NPIX * CIN];          // [pix][ci]
__device__ __align__(128) int8_t g_wq[(size_t)KTAPS * COUT * CIN];  // [kpos][co][ci]
__device__ float g_bint8[COUT];

__device__ __forceinline__ float clamp127(float v) {
    return fminf(127.0f, fmaxf(-127.0f, v));
}

// ---------------------------------------------------------------------------
// Kernel 1: quantize x (NCHW fp32 -> NHWC int8) via smem transpose.
// ---------------------------------------------------------------------------
#define QP 80
__global__ __launch_bounds__(256) void quant_x_kernel(const float* __restrict__ x,
                                                      const float* __restrict__ step_x) {
    __shared__ int8_t s[64 * QP];
    const float st = *step_x;
    const int tid = threadIdx.x;
    const int ptile = blockIdx.x;
    const int ctile = blockIdx.y;
    const int n = ptile >> 6;
    const int hw0 = (ptile & 63) << 6;
    const float* xb = x + (((size_t)(n * CIN + ctile * 64)) << 12) + hw0;

#pragma unroll
    for (int k = 0; k < 4; k++) {
        int idx = tid + 256 * k;
        int ci = idx >> 4;
        int p4 = (idx & 15) << 2;
        float4 f = *(const float4*)(xb + (((size_t)ci) << 12) + p4);
        s[(p4 + 0) * QP + ci] = (int8_t)clamp127(rintf(__fdiv_rn(f.x, st)));
        s[(p4 + 1) * QP + ci] = (int8_t)clamp127(rintf(__fdiv_rn(f.y, st)));
        s[(p4 + 2) * QP + ci] = (int8_t)clamp127(rintf(__fdiv_rn(f.z, st)));
        s[(p4 + 3) * QP + ci] = (int8_t)clamp127(rintf(__fdiv_rn(f.w, st)));
    }
    __syncthreads();
    {
        int p = tid >> 2;
        int ch = (tid & 3) * 16;
        int4 v = *(const int4*)(s + p * QP + ch);
        *(int4*)(g_xq + (size_t)((n << 12) + hw0 + p) * CIN + ctile * 64 + ch) = v;
    }
}

// ---------------------------------------------------------------------------
// Kernel 2: quantize w  (OIHW fp32 -> [kpos][co][ci] int8)
// ---------------------------------------------------------------------------
__global__ void quant_w_kernel(const float* __restrict__ w,
                               const float* __restrict__ step_w) {
    float s = *step_w;
    int idx = blockIdx.x * 256 + threadIdx.x;
    if (idx >= KTAPS * COUT * CIN) return;
    int kpos = idx / (COUT * CIN);
    int r = idx % (COUT * CIN);
    int co = r / CIN;
    int ci = r % CIN;
    float v = clamp127(rintf(__fdiv_rn(w[(size_t)(co * CIN + ci) * KTAPS + kpos], s)));
    g_wq[idx] = (int8_t)v;
}

// ---------------------------------------------------------------------------
// Kernel 3: quantized bias
// ---------------------------------------------------------------------------
__global__ void bias_kernel(const float* __restrict__ bias,
                            const float* __restrict__ step_b,
                            const float* __restrict__ step_x,
                            const float* __restrict__ step_w,
                            const float* __restrict__ shift) {
    int co = blockIdx.x * blockDim.x + threadIdx.x;
    if (co >= COUT) return;
    float sb = *step_b;
    float xs = __fdiv_rn(1.0f, *step_x);
    float ws = __fdiv_rn(1.0f, *step_w);
    float sh = *shift;
    float bi = clamp127(rintf(__fdiv_rn(bias[co], sb)));
    float bdeq = __fmul_rn(bi, sb);
    float t = __fmul_rn(__fmul_rn(__fmul_rn(bdeq, sh), xs), ws);
    g_bint8[co] = clamp127(rintf(t));
}

// ---------------------------------------------------------------------------
// Kernel 4: HYBRID conv — 8 IMMA warps + 8 dp4a warps, block 512.
//   CTA tile 64co x 128pix. Canonical SW pipeline in both groups.
//   warps 0..7  : mma.sync m16n8k32, taps 0..5  (60 stages)
//   warps 8..15 : dp4a 8co x 4pix,  taps 6..8  (30 stages, ILP-restructured)
// ---------------------------------------------------------------------------
#define TAPS_I 6
#define NSI (TAPS_I * 10)
#define NSD ((KTAPS - TAPS_I) * 10)
#define BSTR 48     // dp4a B-tile row stride (conflict-free per 8-lane phase)

__device__ __forceinline__ void mma_s8(int* c, const uint32_t* a, const uint32_t* b) {
    asm volatile(
        "mma.sync.aligned.m16n8k32.row.col.s32.s8.s8.s32 "
        "{%0,%1,%2,%3}, {%4,%5,%6,%7}, {%8,%9}, {%0,%1,%2,%3};"
        : "+r"(c[0]), "+r"(c[1]), "+r"(c[2]), "+r"(c[3])
        : "r"(a[0]), "r"(a[1]), "r"(a[2]), "r"(a[3]),
          "r"(b[0]), "r"(b[1]));
}

__global__ __launch_bounds__(512, 1)
void conv_hybrid_kernel(float* __restrict__ out, const float* __restrict__ shift_ptr) {
    __shared__ __align__(16) int8_t sAi[2][64 * 32];       // IMMA weights (dbuf)
    __shared__ __align__(16) int8_t sBi[2][128 * 32];      // IMMA acts (dbuf)
    __shared__ __align__(16) int8_t sAd[2][64 * 32];       // dp4a weights (dbuf)
    __shared__ __align__(16) int8_t sBd[2][128 * BSTR];    // dp4a acts (dbuf)
    __shared__ int pint[64 * 128];                         // dp4a partials [co][pix]

    const int tid = threadIdx.x;
    const int pix_base = blockIdx.x * 128;
    const int co_base = blockIdx.y * 64;
    const int n = pix_base >> 12;
    const int H0 = (pix_base & 4095) >> 6;      // CTA covers image rows H0, H0+1

    int acc[2][4][4];    // IMMA accs (tid<256)

    if (tid < 256) {
        // ============================ IMMA group ============================
        const int wid = tid >> 5, lane = tid & 31;
        const int warp_m = wid >> 2, warp_n = wid & 3;
        const int qq = lane & 3, rr = lane >> 2;

#pragma unroll
        for (int i = 0; i < 2; i++)
#pragma unroll
            for (int j = 0; j < 4; j++)
#pragma unroll
                for (int k = 0; k < 4; k++) acc[i][j][k] = 0;

        const int rowT = tid >> 1;
        const int half = tid & 1;
        const int hB = H0 + (rowT >> 6);
        const int wB = rowT & 63;

        auto fetchI = [&](int st, int4& av, int4& bv) {
            int kpos = st / 10, ck = st - kpos * 10;
            int dh = kpos / 3 - 1, dw = kpos % 3 - 1;
            if (tid < 128)
                av = *(const int4*)(g_wq + ((size_t)kpos * COUT + co_base + rowT) * CIN + ck * 32 + half * 16);
            int hs = hB + dh, ws = wB + dw;
            bv = make_int4(0, 0, 0, 0);
            if (hs >= 0 && hs < 64 && ws >= 0 && ws < 64)
                bv = *(const int4*)(g_xq + (size_t)((n << 12) + (hs << 6) + ws) * CIN + ck * 32 + half * 16);
        };

        int4 av, bv;
        fetchI(0, av, bv);
        if (tid < 128) *(int4*)(sAi[0] + rowT * 32 + half * 16) = av;
        *(int4*)(sBi[0] + rowT * 32 + half * 16) = bv;
        fetchI(1, av, bv);

        for (int i = 0; i < NSI; i++) {
            asm volatile("bar.sync 1, 256;" ::: "memory");
            const int slot = i & 1;

            if (i + 1 < NSI) {
                const int ns = (i + 1) & 1;
                if (tid < 128) *(int4*)(sAi[ns] + rowT * 32 + half * 16) = av;
                *(int4*)(sBi[ns] + rowT * 32 + half * 16) = bv;
            }
            if (i + 2 < NSI) fetchI(i + 2, av, bv);

            const uint32_t* sA32 = (const uint32_t*)sAi[slot];
            const uint32_t* sB32 = (const uint32_t*)sBi[slot];
            uint32_t a[2][4], b[4][2];
#pragma unroll
            for (int mt = 0; mt < 2; mt++) {
                int row = warp_m * 32 + mt * 16 + rr;
                a[mt][0] = sA32[row * 8 + qq];
                a[mt][1] = sA32[(row + 8) * 8 + qq];
                a[mt][2] = sA32[row * 8 + 4 + qq];
                a[mt][3] = sA32[(row + 8) * 8 + 4 + qq];
            }
#pragma unroll
            for (int nt = 0; nt < 4; nt++) {
                int col = warp_n * 32 + nt * 8 + rr;
                b[nt][0] = sB32[col * 8 + qq];
                b[nt][1] = sB32[col * 8 + 4 + qq];
            }
#pragma unroll
            for (int mt = 0; mt < 2; mt++)
#pragma unroll
                for (int nt = 0; nt < 4; nt++)
                    mma_s8(acc[mt][nt], a[mt], b[nt]);
        }
    } else {
        // ============================ dp4a group ============================
        const int dt = tid - 256;              // 0..255
        const int lane = dt & 31;
        const int cog = dt >> 5;               // warp-uniform co group, 0..7
        const int pig = lane;                  // pixel group, 0..31

        int accD[8][4];                        // [co][pix]
#pragma unroll
        for (int a = 0; a < 8; a++)
#pragma unroll
            for (int b = 0; b < 4; b++) accD[a][b] = 0;

        const int rowL = dt >> 1;              // 0..127
        const int halfL = dt & 1;
        const int hL = H0 + (rowL >> 6);
        const int wL = rowL & 63;

        auto fetchD = [&](int st, int4& av, int4& bv) {
            int kpos = TAPS_I + st / 10, ck = st % 10;
            int dh = kpos / 3 - 1, dw = kpos % 3 - 1;
            if (dt < 128)
                av = *(const int4*)(g_wq + ((size_t)kpos * COUT + co_base + rowL) * CIN + ck * 32 + halfL * 16);
            int hs = hL + dh, ws = wL + dw;
            bv = make_int4(0, 0, 0, 0);
            if (hs >= 0 && hs < 64 && ws >= 0 && ws < 64)
                bv = *(const int4*)(g_xq + (size_t)((n << 12) + (hs << 6) + ws) * CIN + ck * 32 + halfL * 16);
        };

        int4 avD, bvD;
        fetchD(0, avD, bvD);
        if (dt < 128) *(int4*)(sAd[0] + rowL * 32 + halfL * 16) = avD;
        *(int4*)(sBd[0] + rowL * BSTR + halfL * 16) = bvD;
        fetchD(1, avD, bvD);

        for (int i = 0; i < NSD; i++) {
            asm volatile("bar.sync 2, 256;" ::: "memory");
            const int slot = i & 1;

            if (i + 1 < NSD) {
                const int ns = (i + 1) & 1;
                if (dt < 128) *(int4*)(sAd[ns] + rowL * 32 + halfL * 16) = avD;
                *(int4*)(sBd[ns] + rowL * BSTR + halfL * 16) = bvD;
            }
            if (i + 2 < NSD) fetchD(i + 2, avD, bvD);

            // ---- ILP-restructured compute: all bq first, stream aq ----
            int4 bq[8];   // [jj][s16]
#pragma unroll
            for (int jj = 0; jj < 4; jj++) {
                bq[jj * 2 + 0] = *(const int4*)(sBd[slot] + (pig + 32 * jj) * BSTR + 0);
                bq[jj * 2 + 1] = *(const int4*)(sBd[slot] + (pig + 32 * jj) * BSTR + 16);
            }
#pragma unroll
            for (int c = 0; c < 8; c++) {
                int4 a0 = *(const int4*)(sAd[slot] + (cog * 8 + c) * 32);
                int4 a1 = *(const int4*)(sAd[slot] + (cog * 8 + c) * 32 + 16);
#pragma unroll
                for (int jj = 0; jj < 4; jj++) {
                    int acd = accD[c][jj];
                    acd = __dp4a(a0.x, bq[jj * 2].x, acd);
                    acd = __dp4a(a0.y, bq[jj * 2].y, acd);
                    acd = __dp4a(a0.z, bq[jj * 2].z, acd);
                    acd = __dp4a(a0.w, bq[jj * 2].w, acd);
                    acd = __dp4a(a1.x, bq[jj * 2 + 1].x, acd);
                    acd = __dp4a(a1.y, bq[jj * 2 + 1].y, acd);
                    acd = __dp4a(a1.z, bq[jj * 2 + 1].z, acd);
                    acd = __dp4a(a1.w, bq[jj * 2 + 1].w, acd);
                    accD[c][jj] = acd;
                }
            }
        }

        // write partials
#pragma unroll
        for (int c = 0; c < 8; c++)
#pragma unroll
            for (int jj = 0; jj < 4; jj++)
                pint[(cog * 8 + c) * 128 + pig + 32 * jj] = accD[c][jj];
    }

    __syncthreads();

    // =================== merge + epilogue (IMMA warps) ===================
    if (tid < 256) {
        const int wid = tid >> 5, lane = tid & 31;
        const int warp_m = wid >> 2, warp_n = wid & 3;
        const int qq = lane & 3, rr = lane >> 2;
        const float shift = *shift_ptr;
        const int ohw_base = pix_base & 4095;

#pragma unroll
        for (int mt = 0; mt < 2; mt++) {
#pragma unroll
            for (int hh = 0; hh < 2; hh++) {
                int co_l = warp_m * 32 + mt * 16 + rr + hh * 8;
                int co = co_base + co_l;
                float bb = g_bint8[co];
#pragma unroll
                for (int nt = 0; nt < 4; nt++) {
                    int pix_l = warp_n * 32 + nt * 8 + qq * 2;
                    int a0 = acc[mt][nt][hh * 2 + 0] + pint[co_l * 128 + pix_l];
                    int a1 = acc[mt][nt][hh * 2 + 1] + pint[co_l * 128 + pix_l + 1];
                    float v0 = clamp127(rintf(__int2float_rn(a0) * shift));
                    float v1 = clamp127(rintf(__int2float_rn(a1) * shift));
                    v0 = clamp127(v0 + bb);
                    v1 = clamp127(v1 + bb);
                    float* op = out + (((size_t)(n * COUT + co)) << 12) + ohw_base + pix_l;
                    *(float2*)op = make_float2(v0, v1);
                }
            }
        }
    }
}

// ---------------------------------------------------------------------------
extern "C" void kernel_launch(void* const* d_in, const int* in_sizes, int n_in,
                              void* d_out, int out_size) {
    const float* x = (const float*)d_in[0];
    const float* wt = (const float*)d_in[1];
    const float* bias = (const float*)d_in[2];
    const float* step_x = (const float*)d_in[3];
    const float* step_w = (const float*)d_in[4];
    const float* step_b = (const float*)d_in[5];
    const float* shift = (const float*)d_in[6];
    float* out = (float*)d_out;

    quant_x_kernel<<<dim3(1024, 5), 256>>>(x, step_x);

    int wtotal = KTAPS * COUT * CIN;
    quant_w_kernel<<<(wtotal + 255) / 256, 256>>>(wt, step_w);

    bias_kernel<<<2, 160>>>(bias, step_b, step_x, step_w, shift);

    conv_hybrid_kernel<<<dim3(NPIX / 128, COUT / 64), 512>>>(out, shift);
}

// round 8
// speedup vs baseline: 1.1051x; 1.1051x over previous
#include <cuda_runtime.h>
#include <stdint.h>

#define CIN   320
#define COUT  320
#define KTAPS 9
#define NPIX  65536
#define HWSZ  4096

// scratch (__device__ globals: allocation-free rule)
__device__ __align__(128) int8_t g_xq[(size_t)NPIX * CIN];          // [pix][ci]
__device__ __align__(128) int8_t g_wq[(size_t)KTAPS * COUT * CIN];  // [kpos][co][ci]
__device__ float g_bint8[COUT];

__device__ __forceinline__ float clamp127(float v) {
    return fminf(127.0f, fmaxf(-127.0f, v));
}

// ---------------------------------------------------------------------------
// Kernel 1: quantize x (NCHW fp32 -> NHWC int8) via smem transpose.
// ---------------------------------------------------------------------------
#define QP 80
__global__ __launch_bounds__(256) void quant_x_kernel(const float* __restrict__ x,
                                                      const float* __restrict__ step_x) {
    __shared__ int8_t s[64 * QP];
    const float st = *step_x;
    const int tid = threadIdx.x;
    const int ptile = blockIdx.x;
    const int ctile = blockIdx.y;
    const int n = ptile >> 6;
    const int hw0 = (ptile & 63) << 6;
    const float* xb = x + (((size_t)(n * CIN + ctile * 64)) << 12) + hw0;

#pragma unroll
    for (int k = 0; k < 4; k++) {
        int idx = tid + 256 * k;
        int ci = idx >> 4;
        int p4 = (idx & 15) << 2;
        float4 f = *(const float4*)(xb + (((size_t)ci) << 12) + p4);
        s[(p4 + 0) * QP + ci] = (int8_t)clamp127(rintf(__fdiv_rn(f.x, st)));
        s[(p4 + 1) * QP + ci] = (int8_t)clamp127(rintf(__fdiv_rn(f.y, st)));
        s[(p4 + 2) * QP + ci] = (int8_t)clamp127(rintf(__fdiv_rn(f.z, st)));
        s[(p4 + 3) * QP + ci] = (int8_t)clamp127(rintf(__fdiv_rn(f.w, st)));
    }
    __syncthreads();
    {
        int p = tid >> 2;
        int ch = (tid & 3) * 16;
        int4 v = *(const int4*)(s + p * QP + ch);
        *(int4*)(g_xq + (size_t)((n << 12) + hw0 + p) * CIN + ctile * 64 + ch) = v;
    }
}

// ---------------------------------------------------------------------------
// Kernel 2: quantize w  (OIHW fp32 -> [kpos][co][ci] int8)
// ---------------------------------------------------------------------------
__global__ void quant_w_kernel(const float* __restrict__ w,
                               const float* __restrict__ step_w) {
    float s = *step_w;
    int idx = blockIdx.x * 256 + threadIdx.x;
    if (idx >= KTAPS * COUT * CIN) return;
    int kpos = idx / (COUT * CIN);
    int r = idx % (COUT * CIN);
    int co = r / CIN;
    int ci = r % CIN;
    float v = clamp127(rintf(__fdiv_rn(w[(size_t)(co * CIN + ci) * KTAPS + kpos], s)));
    g_wq[idx] = (int8_t)v;
}

// ---------------------------------------------------------------------------
// Kernel 3: quantized bias
// ---------------------------------------------------------------------------
__global__ void bias_kernel(const float* __restrict__ bias,
                            const float* __restrict__ step_b,
                            const float* __restrict__ step_x,
                            const float* __restrict__ step_w,
                            const float* __restrict__ shift) {
    int co = blockIdx.x * blockDim.x + threadIdx.x;
    if (co >= COUT) return;
    float sb = *step_b;
    float xs = __fdiv_rn(1.0f, *step_x);
    float ws = __fdiv_rn(1.0f, *step_w);
    float sh = *shift;
    float bi = clamp127(rintf(__fdiv_rn(bias[co], sb)));
    float bdeq = __fmul_rn(bi, sb);
    float t = __fmul_rn(__fmul_rn(__fmul_rn(bdeq, sh), xs), ws);
    g_bint8[co] = clamp127(rintf(t));
}

// ---------------------------------------------------------------------------
// Kernel 4: UNIFIED conv — every warp runs IMMA (taps 0..5) AND dp4a (taps
//   6..8) interleaved in one instruction stream. CTA = 256 threads, 8 warps,
//   tile 64co x 128pix. dp4a accumulates DIRECTLY into the IMMA fragment
//   accumulators (thread ownership matched) — no merge phase.
//   IMMA: 60 stages (6 taps x 10 ck), dp4a: 30 stages (3 taps x 10 ck),
//   one dp4a stage per two IMMA stages, half (s16) per IMMA stage.
// ---------------------------------------------------------------------------
#define TAPS_I 6
#define NSI (TAPS_I * 10)
#define NSD ((KTAPS - TAPS_I) * 10)
#define ASTRD 48     // sAd row stride (rr*48 -> distinct banks, 16B aligned)
#define BSTRD 40     // sBd row stride (qq*80 -> distinct banks, 8B aligned... cols use +40 steps; 16B loads at col*40 are 8-aligned only — use 2x int2? No: 40*even cols... )

__device__ __forceinline__ void mma_s8(int* c, const uint32_t* a, const uint32_t* b) {
    asm volatile(
        "mma.sync.aligned.m16n8k32.row.col.s32.s8.s8.s32 "
        "{%0,%1,%2,%3}, {%4,%5,%6,%7}, {%8,%9}, {%0,%1,%2,%3};"
        : "+r"(c[0]), "+r"(c[1]), "+r"(c[2]), "+r"(c[3])
        : "r"(a[0]), "r"(a[1]), "r"(a[2]), "r"(a[3]),
          "r"(b[0]), "r"(b[1]));
}

// NOTE on BSTRD: col*40 is 8-byte aligned for even cols only; our cols are
// qq*2 (+1). To keep 16B-aligned vector loads AND bank spread, we use stride
// 48 for sBd as well (col*48: qq*2*48=96*qq -> banks 0,24,16,8 distinct; +48
// for odd col -> banks 12,4,28,20 distinct). 48 is 16B aligned. Redefine:
#undef BSTRD
#define BSTRD 48

__global__ __launch_bounds__(256, 2)
void conv_unified_kernel(float* __restrict__ out, const float* __restrict__ shift_ptr) {
    __shared__ __align__(16) int8_t sAi[2][64 * 32];        // IMMA weights
    __shared__ __align__(16) int8_t sBi[2][128 * 32];       // IMMA acts
    __shared__ __align__(16) int8_t sAd[2][64 * ASTRD];     // dp4a weights
    __shared__ __align__(16) int8_t sBd[2][128 * BSTRD];    // dp4a acts

    const int tid = threadIdx.x;
    const int wid = tid >> 5, lane = tid & 31;
    const int warp_m = wid >> 2, warp_n = wid & 3;
    const int qq = lane & 3, rr = lane >> 2;
    const int pix_base = blockIdx.x * 128;
    const int co_base = blockIdx.y * 64;
    const int n = pix_base >> 12;
    const int H0 = (pix_base & 4095) >> 6;

    int acc[2][4][4];
#pragma unroll
    for (int i = 0; i < 2; i++)
#pragma unroll
        for (int j = 0; j < 4; j++)
#pragma unroll
            for (int k = 0; k < 4; k++) acc[i][j][k] = 0;

    // loader geometry (shared by both streams)
    const int rowT = tid >> 1;      // 0..127
    const int half = tid & 1;
    const int hB = H0 + (rowT >> 6);
    const int wB = rowT & 63;

    auto fetchI = [&](int st, int4& av, int4& bv) {
        int kpos = st / 10, ck = st - kpos * 10;
        int dh = kpos / 3 - 1, dw = kpos % 3 - 1;
        if (tid < 128)
            av = *(const int4*)(g_wq + ((size_t)kpos * COUT + co_base + rowT) * CIN + ck * 32 + half * 16);
        int hs = hB + dh, ws = wB + dw;
        bv = make_int4(0, 0, 0, 0);
        if (hs >= 0 && hs < 64 && ws >= 0 && ws < 64)
            bv = *(const int4*)(g_xq + (size_t)((n << 12) + (hs << 6) + ws) * CIN + ck * 32 + half * 16);
    };
    auto fetchD = [&](int st, int4& av, int4& bv) {
        int kpos = TAPS_I + st / 10, ck = st % 10;
        int dh = kpos / 3 - 1, dw = kpos % 3 - 1;
        if (tid < 128)
            av = *(const int4*)(g_wq + ((size_t)kpos * COUT + co_base + rowT) * CIN + ck * 32 + half * 16);
        int hs = hB + dh, ws = wB + dw;
        bv = make_int4(0, 0, 0, 0);
        if (hs >= 0 && hs < 64 && ws >= 0 && ws < 64)
            bv = *(const int4*)(g_xq + (size_t)((n << 12) + (hs << 6) + ws) * CIN + ck * 32 + half * 16);
    };

    int4 avI, bvI, avD, bvD;
    fetchI(0, avI, bvI);
    if (tid < 128) *(int4*)(sAi[0] + rowT * 32 + half * 16) = avI;
    *(int4*)(sBi[0] + rowT * 32 + half * 16) = bvI;
    fetchD(0, avD, bvD);
    if (tid < 128) *(int4*)(sAd[0] + rowT * ASTRD + half * 16) = avD;
    *(int4*)(sBd[0] + rowT * BSTRD + half * 16) = bvD;
    fetchI(1, avI, bvI);
    fetchD(1, avD, bvD);

    // dp4a row/col bases (fragment-matched ownership)
    const int rA0 = warp_m * 32 + rr;          // +mt*16 +hh*8
    const int cB0 = warp_n * 32 + qq * 2;      // +nt*8 +{0,1}

    for (int i = 0; i < NSI; i++) {
        __syncthreads();
        const int slotI = i & 1;
        const int j = i >> 1;            // dp4a stage
        const int slotD = j & 1;
        const int s16 = i & 1;           // which 16B half of dp4a K this IMMA stage handles

        // STS prefetched IMMA stage i+1
        if (i + 1 < NSI) {
            const int ns = (i + 1) & 1;
            if (tid < 128) *(int4*)(sAi[ns] + rowT * 32 + half * 16) = avI;
            *(int4*)(sBi[ns] + rowT * 32 + half * 16) = bvI;
        }
        if (i + 2 < NSI) fetchI(i + 2, avI, bvI);

        // dp4a stream bookkeeping on even stages
        if (s16 == 0) {
            if (j + 1 < NSD) {
                const int nsD = (j + 1) & 1;
                if (tid < 128) *(int4*)(sAd[nsD] + rowT * ASTRD + half * 16) = avD;
                *(int4*)(sBd[nsD] + rowT * BSTRD + half * 16) = bvD;
            }
            if (j + 2 < NSD) fetchD(j + 2, avD, bvD);
        }

        // ---- IMMA compute on slotI ----
        {
            const uint32_t* sA32 = (const uint32_t*)sAi[slotI];
            const uint32_t* sB32 = (const uint32_t*)sBi[slotI];
            uint32_t a[2][4], b[4][2];
#pragma unroll
            for (int mt = 0; mt < 2; mt++) {
                int row = warp_m * 32 + mt * 16 + rr;
                a[mt][0] = sA32[row * 8 + qq];
                a[mt][1] = sA32[(row + 8) * 8 + qq];
                a[mt][2] = sA32[row * 8 + 4 + qq];
                a[mt][3] = sA32[(row + 8) * 8 + 4 + qq];
            }
#pragma unroll
            for (int nt = 0; nt < 4; nt++) {
                int col = warp_n * 32 + nt * 8 + rr;
                b[nt][0] = sB32[col * 8 + qq];
                b[nt][1] = sB32[col * 8 + 4 + qq];
            }
#pragma unroll
            for (int mt = 0; mt < 2; mt++)
#pragma unroll
                for (int nt = 0; nt < 4; nt++)
                    mma_s8(acc[mt][nt], a[mt], b[nt]);
        }

        // ---- dp4a compute: stage j, 16B half s16, accumulate into acc ----
        if (j < NSD) {
            const int8_t* aT = sAd[slotD];
            const int8_t* bT = sBd[slotD];
            // 4 owned rows: (mt,hh)
            int4 ar[4];
#pragma unroll
            for (int mh = 0; mh < 4; mh++) {
                int row = rA0 + (mh >> 1) * 16 + (mh & 1) * 8;   // mt=mh>>1, hh=mh&1
                ar[mh] = *(const int4*)(aT + row * ASTRD + s16 * 16);
            }
#pragma unroll
            for (int nt = 0; nt < 4; nt++) {
                int col = cB0 + nt * 8;
                int4 b0 = *(const int4*)(bT + col * BSTRD + s16 * 16);
                int4 b1 = *(const int4*)(bT + (col + 1) * BSTRD + s16 * 16);
#pragma unroll
                for (int mh = 0; mh < 4; mh++) {
                    const int mt = mh >> 1, hh = mh & 1;
                    int v0 = acc[mt][nt][hh * 2 + 0];
                    int v1 = acc[mt][nt][hh * 2 + 1];
                    v0 = __dp4a(ar[mh].x, b0.x, v0);
                    v1 = __dp4a(ar[mh].x, b1.x, v1);
                    v0 = __dp4a(ar[mh].y, b0.y, v0);
                    v1 = __dp4a(ar[mh].y, b1.y, v1);
                    v0 = __dp4a(ar[mh].z, b0.z, v0);
                    v1 = __dp4a(ar[mh].z, b1.z, v1);
                    v0 = __dp4a(ar[mh].w, b0.w, v0);
                    v1 = __dp4a(ar[mh].w, b1.w, v1);
                    acc[mt][nt][hh * 2 + 0] = v0;
                    acc[mt][nt][hh * 2 + 1] = v1;
                }
            }
        }
    }

    // =================== epilogue (acc holds all 9 taps) ===================
    {
        const float shift = *shift_ptr;
        const int ohw_base = pix_base & 4095;
#pragma unroll
        for (int mt = 0; mt < 2; mt++) {
#pragma unroll
            for (int hh = 0; hh < 2; hh++) {
                int co = co_base + warp_m * 32 + mt * 16 + rr + hh * 8;
                float bb = g_bint8[co];
#pragma unroll
                for (int nt = 0; nt < 4; nt++) {
                    int pix_l = warp_n * 32 + nt * 8 + qq * 2;
                    int a0 = acc[mt][nt][hh * 2 + 0];
                    int a1 = acc[mt][nt][hh * 2 + 1];
                    float v0 = clamp127(rintf(__int2float_rn(a0) * shift));
                    float v1 = clamp127(rintf(__int2float_rn(a1) * shift));
                    v0 = clamp127(v0 + bb);
                    v1 = clamp127(v1 + bb);
                    float* op = out + (((size_t)(n * COUT + co)) << 12) + ohw_base + pix_l;
                    *(float2*)op = make_float2(v0, v1);
                }
            }
        }
    }
}

// ---------------------------------------------------------------------------
extern "C" void kernel_launch(void* const* d_in, const int* in_sizes, int n_in,
                              void* d_out, int out_size) {
    const float* x = (const float*)d_in[0];
    const float* wt = (const float*)d_in[1];
    const float* bias = (const float*)d_in[2];
    const float* step_x = (const float*)d_in[3];
    const float* step_w = (const float*)d_in[4];
    const float* step_b = (const float*)d_in[5];
    const float* shift = (const float*)d_in[6];
    float* out = (float*)d_out;

    quant_x_kernel<<<dim3(1024, 5), 256>>>(x, step_x);

    int wtotal = KTAPS * COUT * CIN;
    quant_w_kernel<<<(wtotal + 255) / 256, 256>>>(wt, step_w);

    bias_kernel<<<2, 160>>>(bias, step_b, step_x, step_w, shift);

    conv_unified_kernel<<<dim3(NPIX / 128, COUT / 64), 256>>>(out, shift);
}

// round 9
// speedup vs baseline: 1.1672x; 1.0562x over previous
#include <cuda_runtime.h>
#include <stdint.h>

#define CIN   320
#define COUT  320
#define KTAPS 9
#define NPIX  65536
#define HWSZ  4096

// scratch (__device__ globals: allocation-free rule)
__device__ __align__(128) int8_t g_xq[(size_t)NPIX * CIN];          // [pix][ci]
__device__ __align__(128) int8_t g_wq[(size_t)KTAPS * COUT * CIN];  // [kpos][co][ci]
__device__ float g_bint8[COUT];

__device__ __forceinline__ float clamp127(float v) {
    return fminf(127.0f, fmaxf(-127.0f, v));
}

// ---------------------------------------------------------------------------
// Kernel 1: quantize x (NCHW fp32 -> NHWC int8) via smem transpose.
// ---------------------------------------------------------------------------
#define QP 80
__global__ __launch_bounds__(256) void quant_x_kernel(const float* __restrict__ x,
                                                      const float* __restrict__ step_x) {
    __shared__ int8_t s[64 * QP];
    const float st = *step_x;
    const int tid = threadIdx.x;
    const int ptile = blockIdx.x;
    const int ctile = blockIdx.y;
    const int n = ptile >> 6;
    const int hw0 = (ptile & 63) << 6;
    const float* xb = x + (((size_t)(n * CIN + ctile * 64)) << 12) + hw0;

#pragma unroll
    for (int k = 0; k < 4; k++) {
        int idx = tid + 256 * k;
        int ci = idx >> 4;
        int p4 = (idx & 15) << 2;
        float4 f = *(const float4*)(xb + (((size_t)ci) << 12) + p4);
        s[(p4 + 0) * QP + ci] = (int8_t)clamp127(rintf(__fdiv_rn(f.x, st)));
        s[(p4 + 1) * QP + ci] = (int8_t)clamp127(rintf(__fdiv_rn(f.y, st)));
        s[(p4 + 2) * QP + ci] = (int8_t)clamp127(rintf(__fdiv_rn(f.z, st)));
        s[(p4 + 3) * QP + ci] = (int8_t)clamp127(rintf(__fdiv_rn(f.w, st)));
    }
    __syncthreads();
    {
        int p = tid >> 2;
        int ch = (tid & 3) * 16;
        int4 v = *(const int4*)(s + p * QP + ch);
        *(int4*)(g_xq + (size_t)((n << 12) + hw0 + p) * CIN + ctile * 64 + ch) = v;
    }
}

// ---------------------------------------------------------------------------
// Kernel 2: quantize w  (OIHW fp32 -> [kpos][co][ci] int8)
// ---------------------------------------------------------------------------
__global__ void quant_w_kernel(const float* __restrict__ w,
                               const float* __restrict__ step_w) {
    float s = *step_w;
    int idx = blockIdx.x * 256 + threadIdx.x;
    if (idx >= KTAPS * COUT * CIN) return;
    int kpos = idx / (COUT * CIN);
    int r = idx % (COUT * CIN);
    int co = r / CIN;
    int ci = r % CIN;
    float v = clamp127(rintf(__fdiv_rn(w[(size_t)(co * CIN + ci) * KTAPS + kpos], s)));
    g_wq[idx] = (int8_t)v;
}

// ---------------------------------------------------------------------------
// Kernel 3: quantized bias
// ---------------------------------------------------------------------------
__global__ void bias_kernel(const float* __restrict__ bias,
                            const float* __restrict__ step_b,
                            const float* __restrict__ step_x,
                            const float* __restrict__ step_w,
                            const float* __restrict__ shift) {
    int co = blockIdx.x * blockDim.x + threadIdx.x;
    if (co >= COUT) return;
    float sb = *step_b;
    float xs = __fdiv_rn(1.0f, *step_x);
    float ws = __fdiv_rn(1.0f, *step_w);
    float sh = *shift;
    float bi = clamp127(rintf(__fdiv_rn(bias[co], sb)));
    float bdeq = __fmul_rn(bi, sb);
    float t = __fmul_rn(__fmul_rn(__fmul_rn(bdeq, sh), xs), ws);
    g_bint8[co] = clamp127(rintf(t));
}

// ---------------------------------------------------------------------------
// Kernel 4: UNIFIED conv, K=64 stages.
//   8 warps, tile 64co x 128pix. Each warp: IMMA (taps 0..5, 30 stages of
//   K=64) + dp4a (taps 6..8, 15 stages) interleaved; dp4a accumulates into
//   the IMMA fragment accumulators. All tiles row-stride 80B (conflict-free).
// ---------------------------------------------------------------------------
#define TAPS_I 6
#define NSI 30              // 6 taps * 5 ck64
#define NSD 15              // 3 taps * 5 ck64
#define STRD 80             // smem row stride (bytes)
#define SW   20             // row stride in words

// dynamic smem layout (bytes)
#define OFF_AI 0
#define OFF_BI (OFF_AI + 2 * 64 * STRD)      // 10240
#define OFF_AD (OFF_BI + 2 * 128 * STRD)     // 30720
#define OFF_BD (OFF_AD + 2 * 64 * STRD)      // 40960
#define SMEM_TOTAL (OFF_BD + 2 * 128 * STRD) // 61440

__device__ __forceinline__ void mma_s8(int* c, const uint32_t* a, const uint32_t* b) {
    asm volatile(
        "mma.sync.aligned.m16n8k32.row.col.s32.s8.s8.s32 "
        "{%0,%1,%2,%3}, {%4,%5,%6,%7}, {%8,%9}, {%0,%1,%2,%3};"
        : "+r"(c[0]), "+r"(c[1]), "+r"(c[2]), "+r"(c[3])
        : "r"(a[0]), "r"(a[1]), "r"(a[2]), "r"(a[3]),
          "r"(b[0]), "r"(b[1]));
}

__global__ __launch_bounds__(256, 2)
void conv_unified_kernel(float* __restrict__ out, const float* __restrict__ shift_ptr) {
    extern __shared__ __align__(16) int8_t smem[];
    int8_t* sAi = smem + OFF_AI;     // [buf][64 * STRD]
    int8_t* sBi = smem + OFF_BI;     // [buf][128 * STRD]
    int8_t* sAd = smem + OFF_AD;
    int8_t* sBd = smem + OFF_BD;

    const int tid = threadIdx.x;
    const int wid = tid >> 5, lane = tid & 31;
    const int warp_m = wid >> 2, warp_n = wid & 3;
    const int qq = lane & 3, rr = lane >> 2;
    const int pix_base = blockIdx.x * 128;
    const int co_base = blockIdx.y * 64;
    const int n = pix_base >> 12;
    const int H0 = (pix_base & 4095) >> 6;

    int acc[2][4][4];
#pragma unroll
    for (int i = 0; i < 2; i++)
#pragma unroll
        for (int j = 0; j < 4; j++)
#pragma unroll
            for (int k = 0; k < 4; k++) acc[i][j][k] = 0;

    // loader geometry
    const int rowA = tid >> 2;       // 0..63   (A tiles: 64 rows x 64B)
    const int qA   = tid & 3;        //          16B quarter
    const int rowB = tid >> 1;       // 0..127  (B tiles: 128 rows x 64B)
    const int half = tid & 1;        //          32B half
    const int hB = H0 + (rowB >> 6);
    const int wB = rowB & 63;

    // fetch stage st of IMMA stream -> regs
    auto fetchI = [&](int st, int4& av, int4& bv0, int4& bv1) {
        int kpos = st / 5, ck = st % 5;
        int dh = kpos / 3 - 1, dw = kpos % 3 - 1;
        av = *(const int4*)(g_wq + ((size_t)kpos * COUT + co_base + rowA) * CIN + ck * 64 + qA * 16);
        int hs = hB + dh, ws = wB + dw;
        bv0 = make_int4(0, 0, 0, 0);
        bv1 = make_int4(0, 0, 0, 0);
        if (hs >= 0 && hs < 64 && ws >= 0 && ws < 64) {
            const int8_t* p = g_xq + (size_t)((n << 12) + (hs << 6) + ws) * CIN + ck * 64 + half * 32;
            bv0 = *(const int4*)p;
            bv1 = *(const int4*)(p + 16);
        }
    };
    auto fetchD = [&](int st, int4& av, int4& bv0, int4& bv1) {
        int kpos = TAPS_I + st / 5, ck = st % 5;
        int dh = kpos / 3 - 1, dw = kpos % 3 - 1;
        av = *(const int4*)(g_wq + ((size_t)kpos * COUT + co_base + rowA) * CIN + ck * 64 + qA * 16);
        int hs = hB + dh, ws = wB + dw;
        bv0 = make_int4(0, 0, 0, 0);
        bv1 = make_int4(0, 0, 0, 0);
        if (hs >= 0 && hs < 64 && ws >= 0 && ws < 64) {
            const int8_t* p = g_xq + (size_t)((n << 12) + (hs << 6) + ws) * CIN + ck * 64 + half * 32;
            bv0 = *(const int4*)p;
            bv1 = *(const int4*)(p + 16);
        }
    };
    auto stsA = [&](int8_t* base, int buf, const int4& av) {
        *(int4*)(base + buf * 64 * STRD + rowA * STRD + qA * 16) = av;
    };
    auto stsB = [&](int8_t* base, int buf, const int4& bv0, const int4& bv1) {
        int8_t* p = base + buf * 128 * STRD + rowB * STRD + half * 32;
        *(int4*)p = bv0;
        *(int4*)(p + 16) = bv1;
    };

    int4 avI, bvI0, bvI1, avD, bvD0, bvD1;
    fetchI(0, avI, bvI0, bvI1);
    stsA(sAi, 0, avI); stsB(sBi, 0, bvI0, bvI1);
    fetchD(0, avD, bvD0, bvD1);
    stsA(sAd, 0, avD); stsB(sBd, 0, bvD0, bvD1);
    fetchI(1, avI, bvI0, bvI1);
    fetchD(1, avD, bvD0, bvD1);

    // dp4a fragment-matched bases
    const int rA0 = warp_m * 32 + rr;       // +mt*16 +hh*8
    const int cB0 = warp_n * 32 + qq * 2;   // +nt*8 +{0,1}

    for (int i = 0; i < NSI; i++) {
        __syncthreads();
        const int slotI = i & 1;
        const int j = i >> 1;               // dp4a stage (0..14)
        const int slotD = j & 1;

        // STS prefetched IMMA stage i+1; LDG stage i+2
        if (i + 1 < NSI) {
            const int ns = (i + 1) & 1;
            stsA(sAi, ns, avI); stsB(sBi, ns, bvI0, bvI1);
        }
        if (i + 2 < NSI) fetchI(i + 2, avI, bvI0, bvI1);

        // dp4a stream bookkeeping (even IMMA stages)
        if ((i & 1) == 0) {
            if (j + 1 < NSD) {
                const int nsD = (j + 1) & 1;
                stsA(sAd, nsD, avD); stsB(sBd, nsD, bvD0, bvD1);
            }
            if (j + 2 < NSD) fetchD(j + 2, avD, bvD0, bvD1);
        }

        // ---- IMMA compute on slotI: 2 k32 sub-blocks ----
        {
            const uint32_t* sA32 = (const uint32_t*)(sAi + slotI * 64 * STRD);
            const uint32_t* sB32 = (const uint32_t*)(sBi + slotI * 128 * STRD);
#pragma unroll
            for (int kk = 0; kk < 2; kk++) {
                uint32_t a[2][4], b[4][2];
#pragma unroll
                for (int mt = 0; mt < 2; mt++) {
                    int row = warp_m * 32 + mt * 16 + rr;
                    a[mt][0] = sA32[row * SW + kk * 8 + qq];
                    a[mt][1] = sA32[(row + 8) * SW + kk * 8 + qq];
                    a[mt][2] = sA32[row * SW + kk * 8 + 4 + qq];
                    a[mt][3] = sA32[(row + 8) * SW + kk * 8 + 4 + qq];
                }
#pragma unroll
                for (int nt = 0; nt < 4; nt++) {
                    int col = warp_n * 32 + nt * 8 + rr;
                    b[nt][0] = sB32[col * SW + kk * 8 + qq];
                    b[nt][1] = sB32[col * SW + kk * 8 + 4 + qq];
                }
#pragma unroll
                for (int mt = 0; mt < 2; mt++)
#pragma unroll
                    for (int nt = 0; nt < 4; nt++)
                        mma_s8(acc[mt][nt], a[mt], b[nt]);
            }
        }

        // ---- dp4a compute: stage j, two 16B quarters per IMMA stage ----
        {
            const int8_t* aT = sAd + slotD * 64 * STRD;
            const int8_t* bT = sBd + slotD * 128 * STRD;
#pragma unroll
            for (int hq = 0; hq < 2; hq++) {
                const int s16 = 2 * (i & 1) + hq;    // 0..3 across the stage pair
                int4 ar[4];
#pragma unroll
                for (int mh = 0; mh < 4; mh++) {
                    int row = rA0 + (mh >> 1) * 16 + (mh & 1) * 8;
                    ar[mh] = *(const int4*)(aT + row * STRD + s16 * 16);
                }
#pragma unroll
                for (int nt = 0; nt < 4; nt++) {
                    int col = cB0 + nt * 8;
                    int4 b0 = *(const int4*)(bT + col * STRD + s16 * 16);
                    int4 b1 = *(const int4*)(bT + (col + 1) * STRD + s16 * 16);
#pragma unroll
                    for (int mh = 0; mh < 4; mh++) {
                        const int mt = mh >> 1, hh = mh & 1;
                        int v0 = acc[mt][nt][hh * 2 + 0];
                        int v1 = acc[mt][nt][hh * 2 + 1];
                        v0 = __dp4a(ar[mh].x, b0.x, v0);
                        v1 = __dp4a(ar[mh].x, b1.x, v1);
                        v0 = __dp4a(ar[mh].y, b0.y, v0);
                        v1 = __dp4a(ar[mh].y, b1.y, v1);
                        v0 = __dp4a(ar[mh].z, b0.z, v0);
                        v1 = __dp4a(ar[mh].z, b1.z, v1);
                        v0 = __dp4a(ar[mh].w, b0.w, v0);
                        v1 = __dp4a(ar[mh].w, b1.w, v1);
                        acc[mt][nt][hh * 2 + 0] = v0;
                        acc[mt][nt][hh * 2 + 1] = v1;
                    }
                }
            }
        }
    }

    // =================== epilogue (acc holds all 9 taps) ===================
    {
        const float shift = *shift_ptr;
        const int ohw_base = pix_base & 4095;
#pragma unroll
        for (int mt = 0; mt < 2; mt++) {
#pragma unroll
            for (int hh = 0; hh < 2; hh++) {
                int co = co_base + warp_m * 32 + mt * 16 + rr + hh * 8;
                float bb = g_bint8[co];
#pragma unroll
                for (int nt = 0; nt < 4; nt++) {
                    int pix_l = warp_n * 32 + nt * 8 + qq * 2;
                    int a0 = acc[mt][nt][hh * 2 + 0];
                    int a1 = acc[mt][nt][hh * 2 + 1];
                    float v0 = clamp127(rintf(__int2float_rn(a0) * shift));
                    float v1 = clamp127(rintf(__int2float_rn(a1) * shift));
                    v0 = clamp127(v0 + bb);
                    v1 = clamp127(v1 + bb);
                    float* op = out + (((size_t)(n * COUT + co)) << 12) + ohw_base + pix_l;
                    *(float2*)op = make_float2(v0, v1);
                }
            }
        }
    }
}

// ---------------------------------------------------------------------------
extern "C" void kernel_launch(void* const* d_in, const int* in_sizes, int n_in,
                              void* d_out, int out_size) {
    const float* x = (const float*)d_in[0];
    const float* wt = (const float*)d_in[1];
    const float* bias = (const float*)d_in[2];
    const float* step_x = (const float*)d_in[3];
    const float* step_w = (const float*)d_in[4];
    const float* step_b = (const float*)d_in[5];
    const float* shift = (const float*)d_in[6];
    float* out = (float*)d_out;

    cudaFuncSetAttribute(conv_unified_kernel,
                         cudaFuncAttributeMaxDynamicSharedMemorySize, SMEM_TOTAL);

    quant_x_kernel<<<dim3(1024, 5), 256>>>(x, step_x);

    int wtotal = KTAPS * COUT * CIN;
    quant_w_kernel<<<(wtotal + 255) / 256, 256>>>(wt, step_w);

    bias_kernel<<<2, 160>>>(bias, step_b, step_x, step_w, shift);

    conv_unified_kernel<<<dim3(NPIX / 128, COUT / 64), 256, SMEM_TOTAL>>>(out, shift);
}

// round 10
// speedup vs baseline: 1.2457x; 1.0673x over previous
#include <cuda_runtime.h>
#include <stdint.h>

#define CIN   320
#define COUT  320
#define KTAPS 9
#define NPIX  65536
#define HWSZ  4096

// scratch (__device__ globals: allocation-free rule)
__device__ __align__(128) int8_t g_xq[(size_t)NPIX * CIN];          // [pix][ci]
__device__ __align__(128) int8_t g_wq[(size_t)KTAPS * COUT * CIN];  // [kpos][co][ci]
__device__ float g_bint8[COUT];

__device__ __forceinline__ float clamp127(float v) {
    return fminf(127.0f, fmaxf(-127.0f, v));
}

// ---------------------------------------------------------------------------
// Kernel 1: quantize x (NCHW fp32 -> NHWC int8) via smem transpose.
// ---------------------------------------------------------------------------
#define QP 80
__global__ __launch_bounds__(256) void quant_x_kernel(const float* __restrict__ x,
                                                      const float* __restrict__ step_x) {
    __shared__ int8_t s[64 * QP];
    const float st = *step_x;
    const int tid = threadIdx.x;
    const int ptile = blockIdx.x;
    const int ctile = blockIdx.y;
    const int n = ptile >> 6;
    const int hw0 = (ptile & 63) << 6;
    const float* xb = x + (((size_t)(n * CIN + ctile * 64)) << 12) + hw0;

#pragma unroll
    for (int k = 0; k < 4; k++) {
        int idx = tid + 256 * k;
        int ci = idx >> 4;
        int p4 = (idx & 15) << 2;
        float4 f = *(const float4*)(xb + (((size_t)ci) << 12) + p4);
        s[(p4 + 0) * QP + ci] = (int8_t)clamp127(rintf(__fdiv_rn(f.x, st)));
        s[(p4 + 1) * QP + ci] = (int8_t)clamp127(rintf(__fdiv_rn(f.y, st)));
        s[(p4 + 2) * QP + ci] = (int8_t)clamp127(rintf(__fdiv_rn(f.z, st)));
        s[(p4 + 3) * QP + ci] = (int8_t)clamp127(rintf(__fdiv_rn(f.w, st)));
    }
    __syncthreads();
    {
        int p = tid >> 2;
        int ch = (tid & 3) * 16;
        int4 v = *(const int4*)(s + p * QP + ch);
        *(int4*)(g_xq + (size_t)((n << 12) + hw0 + p) * CIN + ctile * 64 + ch) = v;
    }
}

// ---------------------------------------------------------------------------
// Kernel 2: quantize w  (OIHW fp32 -> [kpos][co][ci] int8)
// ---------------------------------------------------------------------------
__global__ void quant_w_kernel(const float* __restrict__ w,
                               const float* __restrict__ step_w) {
    float s = *step_w;
    int idx = blockIdx.x * 256 + threadIdx.x;
    if (idx >= KTAPS * COUT * CIN) return;
    int kpos = idx / (COUT * CIN);
    int r = idx % (COUT * CIN);
    int co = r / CIN;
    int ci = r % CIN;
    float v = clamp127(rintf(__fdiv_rn(w[(size_t)(co * CIN + ci) * KTAPS + kpos], s)));
    g_wq[idx] = (int8_t)v;
}

// ---------------------------------------------------------------------------
// Kernel 3: quantized bias
// ---------------------------------------------------------------------------
__global__ void bias_kernel(const float* __restrict__ bias,
                            const float* __restrict__ step_b,
                            const float* __restrict__ step_x,
                            const float* __restrict__ step_w,
                            const float* __restrict__ shift) {
    int co = blockIdx.x * blockDim.x + threadIdx.x;
    if (co >= COUT) return;
    float sb = *step_b;
    float xs = __fdiv_rn(1.0f, *step_x);
    float ws = __fdiv_rn(1.0f, *step_w);
    float sh = *shift;
    float bi = clamp127(rintf(__fdiv_rn(bias[co], sb)));
    float bdeq = __fmul_rn(bi, sb);
    float t = __fmul_rn(__fmul_rn(__fmul_rn(bdeq, sh), xs), ws);
    g_bint8[co] = clamp127(rintf(t));
}

// ---------------------------------------------------------------------------
// Kernel 4: UNIFIED conv, ~50/50 IMMA/dp4a split by K64 units.
//   45 k64-units total (9 taps x 5 ck64). IMMA stream: units 0..22 (23
//   stages). dp4a stream: units 23..44 (22 stages), one full dp4a stage
//   (4 x 16B quarters) per IMMA stage, accumulating into the same fragment
//   accumulators. 8 warps, tile 64co x 128pix, 2 CTAs/SM.
// ---------------------------------------------------------------------------
#define NSI 23
#define NSD 22
#define UD_BASE NSI         // dp4a units start at 23
#define STRD 80             // smem row stride (bytes), conflict-free
#define SW   20             // row stride in words

// dynamic smem layout (bytes)
#define OFF_AI 0
#define OFF_BI (OFF_AI + 2 * 64 * STRD)      // 10240
#define OFF_AD (OFF_BI + 2 * 128 * STRD)     // 30720
#define OFF_BD (OFF_AD + 2 * 64 * STRD)      // 40960
#define SMEM_TOTAL (OFF_BD + 2 * 128 * STRD) // 61440

__device__ __forceinline__ void mma_s8(int* c, const uint32_t* a, const uint32_t* b) {
    asm volatile(
        "mma.sync.aligned.m16n8k32.row.col.s32.s8.s8.s32 "
        "{%0,%1,%2,%3}, {%4,%5,%6,%7}, {%8,%9}, {%0,%1,%2,%3};"
        : "+r"(c[0]), "+r"(c[1]), "+r"(c[2]), "+r"(c[3])
        : "r"(a[0]), "r"(a[1]), "r"(a[2]), "r"(a[3]),
          "r"(b[0]), "r"(b[1]));
}

__global__ __launch_bounds__(256, 2)
void conv_unified_kernel(float* __restrict__ out, const float* __restrict__ shift_ptr) {
    extern __shared__ __align__(16) int8_t smem[];
    int8_t* sAi = smem + OFF_AI;     // [buf][64 * STRD]
    int8_t* sBi = smem + OFF_BI;     // [buf][128 * STRD]
    int8_t* sAd = smem + OFF_AD;
    int8_t* sBd = smem + OFF_BD;

    const int tid = threadIdx.x;
    const int wid = tid >> 5, lane = tid & 31;
    const int warp_m = wid >> 2, warp_n = wid & 3;
    const int qq = lane & 3, rr = lane >> 2;
    const int pix_base = blockIdx.x * 128;
    const int co_base = blockIdx.y * 64;
    const int n = pix_base >> 12;
    const int H0 = (pix_base & 4095) >> 6;

    int acc[2][4][4];
#pragma unroll
    for (int i = 0; i < 2; i++)
#pragma unroll
        for (int j = 0; j < 4; j++)
#pragma unroll
            for (int k = 0; k < 4; k++) acc[i][j][k] = 0;

    // loader geometry
    const int rowA = tid >> 2;       // 0..63   (A tiles: 64 rows x 64B)
    const int qA   = tid & 3;
    const int rowB = tid >> 1;       // 0..127  (B tiles: 128 rows x 64B)
    const int half = tid & 1;
    const int hB = H0 + (rowB >> 6);
    const int wB = rowB & 63;

    // fetch k64-unit u (kpos = u/5, ck = u%5) -> regs
    auto fetchU = [&](int u, int4& av, int4& bv0, int4& bv1) {
        int kpos = u / 5, ck = u % 5;
        int dh = kpos / 3 - 1, dw = kpos % 3 - 1;
        av = *(const int4*)(g_wq + ((size_t)kpos * COUT + co_base + rowA) * CIN + ck * 64 + qA * 16);
        int hs = hB + dh, ws = wB + dw;
        bv0 = make_int4(0, 0, 0, 0);
        bv1 = make_int4(0, 0, 0, 0);
        if (hs >= 0 && hs < 64 && ws >= 0 && ws < 64) {
            const int8_t* p = g_xq + (size_t)((n << 12) + (hs << 6) + ws) * CIN + ck * 64 + half * 32;
            bv0 = *(const int4*)p;
            bv1 = *(const int4*)(p + 16);
        }
    };
    auto stsA = [&](int8_t* base, int buf, const int4& av) {
        *(int4*)(base + buf * 64 * STRD + rowA * STRD + qA * 16) = av;
    };
    auto stsB = [&](int8_t* base, int buf, const int4& bv0, const int4& bv1) {
        int8_t* p = base + buf * 128 * STRD + rowB * STRD + half * 32;
        *(int4*)p = bv0;
        *(int4*)(p + 16) = bv1;
    };

    int4 avI, bvI0, bvI1, avD, bvD0, bvD1;
    fetchU(0, avI, bvI0, bvI1);
    stsA(sAi, 0, avI); stsB(sBi, 0, bvI0, bvI1);
    fetchU(UD_BASE, avD, bvD0, bvD1);
    stsA(sAd, 0, avD); stsB(sBd, 0, bvD0, bvD1);
    fetchU(1, avI, bvI0, bvI1);
    fetchU(UD_BASE + 1, avD, bvD0, bvD1);

    // dp4a fragment-matched bases
    const int rA0 = warp_m * 32 + rr;       // +mt*16 +hh*8
    const int cB0 = warp_n * 32 + qq * 2;   // +nt*8 +{0,1}

#pragma unroll 1
    for (int i = 0; i < NSI; i++) {
        __syncthreads();
        const int slot = i & 1;

        // STS prefetched stage i+1 (both streams); LDG stage i+2
        if (i + 1 < NSI) {
            const int ns = (i + 1) & 1;
            stsA(sAi, ns, avI); stsB(sBi, ns, bvI0, bvI1);
        }
        if (i + 1 < NSD) {
            const int ns = (i + 1) & 1;
            stsA(sAd, ns, avD); stsB(sBd, ns, bvD0, bvD1);
        }
        if (i + 2 < NSI) fetchU(i + 2, avI, bvI0, bvI1);
        if (i + 2 < NSD) fetchU(UD_BASE + i + 2, avD, bvD0, bvD1);

        // ---- IMMA compute on slot: 2 k32 sub-blocks ----
        {
            const uint32_t* sA32 = (const uint32_t*)(sAi + slot * 64 * STRD);
            const uint32_t* sB32 = (const uint32_t*)(sBi + slot * 128 * STRD);
#pragma unroll
            for (int kk = 0; kk < 2; kk++) {
                uint32_t a[2][4], b[4][2];
#pragma unroll
                for (int mt = 0; mt < 2; mt++) {
                    int row = warp_m * 32 + mt * 16 + rr;
                    a[mt][0] = sA32[row * SW + kk * 8 + qq];
                    a[mt][1] = sA32[(row + 8) * SW + kk * 8 + qq];
                    a[mt][2] = sA32[row * SW + kk * 8 + 4 + qq];
                    a[mt][3] = sA32[(row + 8) * SW + kk * 8 + 4 + qq];
                }
#pragma unroll
                for (int nt = 0; nt < 4; nt++) {
                    int col = warp_n * 32 + nt * 8 + rr;
                    b[nt][0] = sB32[col * SW + kk * 8 + qq];
                    b[nt][1] = sB32[col * SW + kk * 8 + 4 + qq];
                }
#pragma unroll
                for (int mt = 0; mt < 2; mt++)
#pragma unroll
                    for (int nt = 0; nt < 4; nt++)
                        mma_s8(acc[mt][nt], a[mt], b[nt]);
            }
        }

        // ---- dp4a compute: stage i (if < NSD), all 4 quarters ----
        if (i < NSD) {
            const int8_t* aT = sAd + slot * 64 * STRD;
            const int8_t* bT = sBd + slot * 128 * STRD;
#pragma unroll
            for (int s16 = 0; s16 < 4; s16++) {
                int4 ar[4];
#pragma unroll
                for (int mh = 0; mh < 4; mh++) {
                    int row = rA0 + (mh >> 1) * 16 + (mh & 1) * 8;
                    ar[mh] = *(const int4*)(aT + row * STRD + s16 * 16);
                }
#pragma unroll
                for (int nt = 0; nt < 4; nt++) {
                    int col = cB0 + nt * 8;
                    int4 b0 = *(const int4*)(bT + col * STRD + s16 * 16);
                    int4 b1 = *(const int4*)(bT + (col + 1) * STRD + s16 * 16);
#pragma unroll
                    for (int mh = 0; mh < 4; mh++) {
                        const int mt = mh >> 1, hh = mh & 1;
                        int v0 = acc[mt][nt][hh * 2 + 0];
                        int v1 = acc[mt][nt][hh * 2 + 1];
                        v0 = __dp4a(ar[mh].x, b0.x, v0);
                        v1 = __dp4a(ar[mh].x, b1.x, v1);
                        v0 = __dp4a(ar[mh].y, b0.y, v0);
                        v1 = __dp4a(ar[mh].y, b1.y, v1);
                        v0 = __dp4a(ar[mh].z, b0.z, v0);
                        v1 = __dp4a(ar[mh].z, b1.z, v1);
                        v0 = __dp4a(ar[mh].w, b0.w, v0);
                        v1 = __dp4a(ar[mh].w, b1.w, v1);
                        acc[mt][nt][hh * 2 + 0] = v0;
                        acc[mt][nt][hh * 2 + 1] = v1;
                    }
                }
            }
        }
    }

    // =================== epilogue (acc holds all 9 taps) ===================
    {
        const float shift = *shift_ptr;
        const int ohw_base = pix_base & 4095;
#pragma unroll
        for (int mt = 0; mt < 2; mt++) {
#pragma unroll
            for (int hh = 0; hh < 2; hh++) {
                int co = co_base + warp_m * 32 + mt * 16 + rr + hh * 8;
                float bb = g_bint8[co];
#pragma unroll
                for (int nt = 0; nt < 4; nt++) {
                    int pix_l = warp_n * 32 + nt * 8 + qq * 2;
                    int a0 = acc[mt][nt][hh * 2 + 0];
                    int a1 = acc[mt][nt][hh * 2 + 1];
                    float v0 = clamp127(rintf(__int2float_rn(a0) * shift));
                    float v1 = clamp127(rintf(__int2float_rn(a1) * shift));
                    v0 = clamp127(v0 + bb);
                    v1 = clamp127(v1 + bb);
                    float* op = out + (((size_t)(n * COUT + co)) << 12) + ohw_base + pix_l;
                    *(float2*)op = make_float2(v0, v1);
                }
            }
        }
    }
}

// ---------------------------------------------------------------------------
extern "C" void kernel_launch(void* const* d_in, const int* in_sizes, int n_in,
                              void* d_out, int out_size) {
    const float* x = (const float*)d_in[0];
    const float* wt = (const float*)d_in[1];
    const float* bias = (const float*)d_in[2];
    const float* step_x = (const float*)d_in[3];
    const float* step_w = (const float*)d_in[4];
    const float* step_b = (const float*)d_in[5];
    const float* shift = (const float*)d_in[6];
    float* out = (float*)d_out;

    cudaFuncSetAttribute(conv_unified_kernel,
                         cudaFuncAttributeMaxDynamicSharedMemorySize, SMEM_TOTAL);

    quant_x_kernel<<<dim3(1024, 5), 256>>>(x, step_x);

    int wtotal = KTAPS * COUT * CIN;
    quant_w_kernel<<<(wtotal + 255) / 256, 256>>>(wt, step_w);

    bias_kernel<<<2, 160>>>(bias, step_b, step_x, step_w, shift);

    conv_unified_kernel<<<dim3(NPIX / 128, COUT / 64), 256, SMEM_TOTAL>>>(out, shift);
}